// round 13
// baseline (speedup 1.0000x reference)
#include <cuda_runtime.h>
#include <cuda_fp16.h>
#include <cstdint>

#define KDIM 4096
#define KSLICE 2048
#define BK 64
#define NKB (KSLICE / BK)      // 32
#define A_BYTES 16384          // 128 rows x 128B
#define B_BYTES 16384
#define STG_BYTES (A_BYTES + B_BYTES)   // 32768
#define SMEM_BYTES (3 * STG_BYTES)      // 98304

// ---- scratch (static device arrays; no runtime alloc) ----
__device__ __half g_xh[512 * 4096];          // A[m][k] fp16
__device__ __half g_wh[4096ull * 4096];      // B[n][k] fp16
__device__ float  g_part[2ull * 512 * 4096]; // split-K partials

// ============ merged converter (coalesced) ============
__global__ void cvt_kernel(const float* __restrict__ x, const float* __restrict__ w) {
    const int b = blockIdx.x;
    const int t = threadIdx.x;
    if (b < 2048) {
        const int i  = b >> 2;
        const int jl = t >> 1;
        const int q4 = t & 1;
        const int j  = (b & 3) * 128 + jl;
        const float* src = w + (size_t)i * 32768 + j * 64 + q4 * 4;
        float4 f[8];
        #pragma unroll
        for (int p = 0; p < 8; ++p)
            f[p] = *reinterpret_cast<const float4*>(src + p * 8);
        #pragma unroll
        for (int d = 0; d < 4; ++d) {
            __half h[8];
            #pragma unroll
            for (int p = 0; p < 8; ++p)
                h[p] = __float2half_rn((&f[p].x)[d]);
            const int n = i * 8 + q4 * 4 + d;
            *reinterpret_cast<uint4*>(g_wh + (size_t)n * 4096 + j * 8) =
                *reinterpret_cast<uint4*>(h);
        }
    } else {
        const int base = (b - 2048) * 1024 + t;
        __half2* dst = reinterpret_cast<__half2*>(g_xh);
        #pragma unroll
        for (int s = 0; s < 4; ++s) {
            const int i = base + s * 256;
            const float4 v = reinterpret_cast<const float4*>(x)[i];
            dst[2 * i]     = __floats2half2_rn(v.x, v.y);
            dst[2 * i + 1] = __floats2half2_rn(v.z, v.w);
        }
    }
}

// ============ GEMM (split-K) ============
__device__ __forceinline__ uint32_t smem_u32(const void* p) {
    uint32_t a;
    asm("{ .reg .u64 t; cvta.to.shared.u64 t, %1; cvt.u32.u64 %0, t; }" : "=r"(a) : "l"(p));
    return a;
}
__device__ __forceinline__ void cp16(uint32_t dst, const void* src) {
    asm volatile("cp.async.cg.shared.global [%0], [%1], 16;" :: "r"(dst), "l"(src));
}
__device__ __forceinline__ void ldsm_x4(uint32_t* r, uint32_t addr) {
    asm volatile("ldmatrix.sync.aligned.m8n8.x4.shared.b16 {%0,%1,%2,%3}, [%4];"
                 : "=r"(r[0]), "=r"(r[1]), "=r"(r[2]), "=r"(r[3]) : "r"(addr));
}
__device__ __forceinline__ void mma_f16(float* d, const uint32_t* a, const uint32_t* b) {
    asm volatile(
        "mma.sync.aligned.m16n8k16.row.col.f32.f16.f16.f32 "
        "{%0,%1,%2,%3}, {%4,%5,%6,%7}, {%8,%9}, {%0,%1,%2,%3};"
        : "+f"(d[0]), "+f"(d[1]), "+f"(d[2]), "+f"(d[3])
        : "r"(a[0]), "r"(a[1]), "r"(a[2]), "r"(a[3]),
          "r"(b[0]), "r"(b[1]));
}

// CTA 128x128 over half of K; 256 threads, 8 warps of 64x32.
__global__ __launch_bounds__(256, 2)
void octonion_gemm_f16(void)
{
    extern __shared__ char smem[];
    const uint32_t sbase = smem_u32(smem);

    const int tid  = threadIdx.x;
    const int lane = tid & 31;
    const int warp = tid >> 5;
    const int wm   = warp >> 2;          // 0..1 -> 64-row strip
    const int wn   = warp & 3;           // 0..3 -> 32-col strip
    const int row0 = blockIdx.y * 128;
    const int col0 = blockIdx.x * 128;
    const int kz   = blockIdx.z;         // 0,1 -> k slice

    // ---- loader: 4 A + 4 B 16B chunks per thread per stage ----
    const int lr = tid >> 3;             // 0..31
    const int lu = tid & 7;
    const __half* aSrc = g_xh + (size_t)(row0 + lr) * KDIM + kz * KSLICE + lu * 8;
    const __half* bSrc = g_wh + (size_t)(col0 + lr) * KDIM + kz * KSLICE + lu * 8;
    uint32_t dOff[4];
    #pragma unroll
    for (int i = 0; i < 4; ++i) {
        const int r = lr + 32 * i;
        dOff[i] = (uint32_t)(r * 128 + (((uint32_t)lu ^ (r & 7)) << 4));
    }

    // ---- fragment addressing ----
    const int ubit = lane >> 4;
    uint32_t swx[4];
    #pragma unroll
    for (int ks = 0; ks < 4; ++ks)
        swx[ks] = (uint32_t)(((2 * ks + ubit) ^ (lane & 7)) << 4);
    const uint32_t aBase = (uint32_t)((wm * 64 + (lane & 15)) * 128);
    const uint32_t bBase = A_BYTES + (uint32_t)((wn * 32 + (lane & 15)) * 128);

    float acc[4][4][4];
    #pragma unroll
    for (int i = 0; i < 4; ++i)
        #pragma unroll
        for (int j = 0; j < 4; ++j)
            #pragma unroll
            for (int r = 0; r < 4; ++r)
                acc[i][j][r] = 0.0f;

    // ---- prologue: 2 stages in flight ----
    #pragma unroll
    for (int s = 0; s < 2; ++s) {
        const uint32_t so = sbase + s * STG_BYTES;
        #pragma unroll
        for (int i = 0; i < 4; ++i) {
            cp16(so + dOff[i],           aSrc + (size_t)(s * BK) + (size_t)(32 * i) * KDIM);
            cp16(so + A_BYTES + dOff[i], bSrc + (size_t)(s * BK) + (size_t)(32 * i) * KDIM);
        }
        asm volatile("cp.async.commit_group;" ::: "memory");
    }

    int sidx = 0;
    for (int kb = 0; kb < NKB; ++kb) {
        asm volatile("cp.async.wait_group 1;" ::: "memory");
        __syncthreads();

        const uint32_t so = sbase + sidx * STG_BYTES;

        #pragma unroll
        for (int ks = 0; ks < 4; ++ks) {
            uint32_t a[4][4], b[4][2];
            #pragma unroll
            for (int mt = 0; mt < 4; ++mt)
                ldsm_x4(a[mt], so + aBase + mt * 2048u + swx[ks]);
            #pragma unroll
            for (int ntp = 0; ntp < 2; ++ntp) {
                uint32_t t4[4];
                ldsm_x4(t4, so + bBase + ntp * 2048u + swx[ks]);
                b[2 * ntp][0] = t4[0]; b[2 * ntp + 1][0] = t4[1];
                b[2 * ntp][1] = t4[2]; b[2 * ntp + 1][1] = t4[3];
            }
            #pragma unroll
            for (int mt = 0; mt < 4; ++mt)
                #pragma unroll
                for (int nt = 0; nt < 4; ++nt)
                    mma_f16(acc[mt][nt], a[mt], b[nt]);
        }

        if (kb + 2 < NKB) {
            const uint32_t sn = sbase + ((sidx + 2) % 3) * STG_BYTES;
            const size_t ko = (size_t)(kb + 2) * BK;
            #pragma unroll
            for (int i = 0; i < 4; ++i) {
                cp16(sn + dOff[i],           aSrc + ko + (size_t)(32 * i) * KDIM);
                cp16(sn + A_BYTES + dOff[i], bSrc + ko + (size_t)(32 * i) * KDIM);
            }
            asm volatile("cp.async.commit_group;" ::: "memory");
        }
        sidx = (sidx == 2) ? 0 : sidx + 1;
    }

    // ---- epilogue: write fp32 partials (no bias here) ----
    float* part = g_part + (size_t)kz * (512ull * 4096);
    #pragma unroll
    for (int mt = 0; mt < 4; ++mt) {
        const int row = row0 + wm * 64 + mt * 16 + (lane >> 2);
        #pragma unroll
        for (int nt = 0; nt < 4; ++nt) {
            const int col = col0 + wn * 32 + nt * 8 + (lane & 3) * 2;
            float2 o0, o1;
            o0.x = acc[mt][nt][0]; o0.y = acc[mt][nt][1];
            o1.x = acc[mt][nt][2]; o1.y = acc[mt][nt][3];
            *reinterpret_cast<float2*>(part + (size_t)row * KDIM + col) = o0;
            *reinterpret_cast<float2*>(part + (size_t)(row + 8) * KDIM + col) = o1;
        }
    }
}

// ============ reduce: out = p0 + p1 + bias ============
__global__ void reduce_kernel(const float* __restrict__ bias, float* __restrict__ out) {
    const int i = blockIdx.x * 256 + threadIdx.x;     // float4 index (524288 total)
    const float4 a = reinterpret_cast<const float4*>(g_part)[i];
    const float4 b = reinterpret_cast<const float4*>(g_part + 512ull * 4096)[i];
    const float4 bb = reinterpret_cast<const float4*>(bias)[i & 1023];
    float4 o;
    o.x = a.x + b.x + bb.x;
    o.y = a.y + b.y + bb.y;
    o.z = a.z + b.z + bb.z;
    o.w = a.w + b.w + bb.w;
    reinterpret_cast<float4*>(out)[i] = o;
}

extern "C" void kernel_launch(void* const* d_in, const int* in_sizes, int n_in,
                              void* d_out, int out_size)
{
    const float* x    = (const float*)d_in[0];   // [512, 4096]
    const float* w    = (const float*)d_in[1];   // [512, 512, 8, 8]
    const float* bias = (const float*)d_in[2];   // [512, 8] -> flat [4096]
    float* out = (float*)d_out;                  // [512, 4096]

    cvt_kernel<<<2560, 256>>>(x, w);

    cudaFuncSetAttribute(octonion_gemm_f16,
                         cudaFuncAttributeMaxDynamicSharedMemorySize, SMEM_BYTES);
    dim3 grid(KDIM / 128, 512 / 128, 2);         // (32, 4, 2) = 256 CTAs
    octonion_gemm_f16<<<grid, 256, SMEM_BYTES>>>();

    reduce_kernel<<<2048, 256>>>(bias, out);
}

// round 15
// speedup vs baseline: 1.0824x; 1.0824x over previous
#include <cuda_runtime.h>
#include <cuda_fp16.h>
#include <cstdint>

#define KDIM 4096
#define BK 64
#define NKB (KDIM / BK)        // 64
#define A_BYTES 8192           // 64 rows x 128B
#define B_BYTES 16384          // 128 rows x 128B
#define STG_BYTES (A_BYTES + B_BYTES)   // 24576
#define SMEM_BYTES (3 * STG_BYTES)      // 73728

// ---- scratch: fp16 copies (static device arrays; no runtime alloc) ----
__device__ __half g_xh[512 * 4096];          // A[m][k]
__device__ __half g_wh[4096ull * 4096];      // B[n][k]

// ============ merged converter (coalesced) ============
__global__ void cvt_kernel(const float* __restrict__ x, const float* __restrict__ w) {
    const int b = blockIdx.x;
    const int t = threadIdx.x;
    if (b < 2048) {
        const int i  = b >> 2;
        const int jl = t >> 1;
        const int q4 = t & 1;
        const int j  = (b & 3) * 128 + jl;
        const float* src = w + (size_t)i * 32768 + j * 64 + q4 * 4;
        float4 f[8];
        #pragma unroll
        for (int p = 0; p < 8; ++p)
            f[p] = *reinterpret_cast<const float4*>(src + p * 8);
        #pragma unroll
        for (int d = 0; d < 4; ++d) {
            __half h[8];
            #pragma unroll
            for (int p = 0; p < 8; ++p)
                h[p] = __float2half_rn((&f[p].x)[d]);
            const int n = i * 8 + q4 * 4 + d;
            *reinterpret_cast<uint4*>(g_wh + (size_t)n * 4096 + j * 8) =
                *reinterpret_cast<uint4*>(h);
        }
    } else {
        const int base = (b - 2048) * 1024 + t;
        __half2* dst = reinterpret_cast<__half2*>(g_xh);
        #pragma unroll
        for (int s = 0; s < 4; ++s) {
            const int i = base + s * 256;
            const float4 v = reinterpret_cast<const float4*>(x)[i];
            dst[2 * i]     = __floats2half2_rn(v.x, v.y);
            dst[2 * i + 1] = __floats2half2_rn(v.z, v.w);
        }
    }
}

// ============ GEMM ============
__device__ __forceinline__ uint32_t smem_u32(const void* p) {
    uint32_t a;
    asm("{ .reg .u64 t; cvta.to.shared.u64 t, %1; cvt.u32.u64 %0, t; }" : "=r"(a) : "l"(p));
    return a;
}
__device__ __forceinline__ void cp16(uint32_t dst, const void* src) {
    asm volatile("cp.async.cg.shared.global [%0], [%1], 16;" :: "r"(dst), "l"(src));
}
__device__ __forceinline__ void ldsm_x4(uint32_t* r, uint32_t addr) {
    asm volatile("ldmatrix.sync.aligned.m8n8.x4.shared.b16 {%0,%1,%2,%3}, [%4];"
                 : "=r"(r[0]), "=r"(r[1]), "=r"(r[2]), "=r"(r[3]) : "r"(addr));
}
__device__ __forceinline__ void mma_f16(float* d, const uint32_t* a, const uint32_t* b) {
    asm volatile(
        "mma.sync.aligned.m16n8k16.row.col.f32.f16.f16.f32 "
        "{%0,%1,%2,%3}, {%4,%5,%6,%7}, {%8,%9}, {%0,%1,%2,%3};"
        : "+f"(d[0]), "+f"(d[1]), "+f"(d[2]), "+f"(d[3])
        : "r"(a[0]), "r"(a[1]), "r"(a[2]), "r"(a[3]),
          "r"(b[0]), "r"(b[1]));
}

// CTA 64x128, 128 threads, 4 warps each owning a 64x32 output strip. 3 CTAs/SM.
__global__ __launch_bounds__(128, 3)
void octonion_gemm_f16(const float* __restrict__ bias, float* __restrict__ out)
{
    extern __shared__ char smem[];
    const uint32_t sbase = smem_u32(smem);

    const int tid  = threadIdx.x;
    const int lane = tid & 31;
    const int wn   = tid >> 5;           // warp 0..3 -> 32-col strip
    const int row0 = blockIdx.y * 64;
    const int col0 = blockIdx.x * 128;

    // ---- loader: 4 A + 8 B 16B chunks per thread per stage ----
    const int lr = tid >> 3;             // 0..15
    const int lu = tid & 7;
    const __half* aSrc = g_xh + (size_t)(row0 + lr) * KDIM + lu * 8;
    const __half* bSrc = g_wh + (size_t)(col0 + lr) * KDIM + lu * 8;
    uint32_t dOff[8];
    #pragma unroll
    for (int i = 0; i < 8; ++i) {
        const int r = lr + 16 * i;
        dOff[i] = (uint32_t)((r & 63) * 128 + (((uint32_t)lu ^ (r & 7)) << 4));
    }

    // ---- fragment addressing ----
    const int ubit = lane >> 4;
    uint32_t swx[4];
    #pragma unroll
    for (int ks = 0; ks < 4; ++ks)
        swx[ks] = (uint32_t)(((2 * ks + ubit) ^ (lane & 7)) << 4);
    const uint32_t aBase = (uint32_t)((lane & 15) * 128);
    const uint32_t bBase = A_BYTES + (uint32_t)((wn * 32 + (lane & 15)) * 128);

    float acc[4][4][4];
    #pragma unroll
    for (int i = 0; i < 4; ++i)
        #pragma unroll
        for (int j = 0; j < 4; ++j)
            #pragma unroll
            for (int r = 0; r < 4; ++r)
                acc[i][j][r] = 0.0f;

    // ---- prologue: 2 stages in flight ----
    #pragma unroll
    for (int s = 0; s < 2; ++s) {
        const uint32_t so = sbase + s * STG_BYTES;
        #pragma unroll
        for (int i = 0; i < 4; ++i)
            cp16(so + dOff[i], aSrc + (size_t)(s * BK) + (size_t)(16 * i) * KDIM);
        #pragma unroll
        for (int i = 0; i < 8; ++i)
            cp16(so + A_BYTES + dOff[i] + (uint32_t)(i >> 2) * 8192,
                 bSrc + (size_t)(s * BK) + (size_t)(16 * i) * KDIM);
        asm volatile("cp.async.commit_group;" ::: "memory");
    }

    int sidx = 0;
    for (int kb = 0; kb < NKB; ++kb) {
        // Tail-safe drain: in the last two iterations the consumed group could
        // be among the "1 most recent", so wait for ALL groups there.
        if (kb + 2 < NKB)
            asm volatile("cp.async.wait_group 1;" ::: "memory");
        else
            asm volatile("cp.async.wait_group 0;" ::: "memory");
        __syncthreads();

        const uint32_t so = sbase + sidx * STG_BYTES;

        #pragma unroll
        for (int ks = 0; ks < 4; ++ks) {
            uint32_t a[4][4], b[4][2];
            #pragma unroll
            for (int mt = 0; mt < 4; ++mt)
                ldsm_x4(a[mt], so + aBase + mt * 2048u + swx[ks]);
            #pragma unroll
            for (int ntp = 0; ntp < 2; ++ntp) {
                uint32_t t4[4];
                ldsm_x4(t4, so + bBase + ntp * 2048u + swx[ks]);
                b[2 * ntp][0] = t4[0]; b[2 * ntp + 1][0] = t4[1];
                b[2 * ntp][1] = t4[2]; b[2 * ntp + 1][1] = t4[3];
            }
            #pragma unroll
            for (int mt = 0; mt < 4; ++mt)
                #pragma unroll
                for (int nt = 0; nt < 4; ++nt)
                    mma_f16(acc[mt][nt], a[mt], b[nt]);
        }

        if (kb + 2 < NKB) {
            const uint32_t sn = sbase + ((sidx + 2) % 3) * STG_BYTES;
            const size_t ko = (size_t)(kb + 2) * BK;
            #pragma unroll
            for (int i = 0; i < 4; ++i)
                cp16(sn + dOff[i], aSrc + ko + (size_t)(16 * i) * KDIM);
            #pragma unroll
            for (int i = 0; i < 8; ++i)
                cp16(sn + A_BYTES + dOff[i] + (uint32_t)(i >> 2) * 8192,
                     bSrc + ko + (size_t)(16 * i) * KDIM);
            asm volatile("cp.async.commit_group;" ::: "memory");
        }
        sidx = (sidx == 2) ? 0 : sidx + 1;
    }

    // ---- epilogue: + bias, float2 stores ----
    #pragma unroll
    for (int mt = 0; mt < 4; ++mt) {
        const int row = row0 + mt * 16 + (lane >> 2);
        #pragma unroll
        for (int nt = 0; nt < 4; ++nt) {
            const int col = col0 + wn * 32 + nt * 8 + (lane & 3) * 2;
            const float2 bb = *reinterpret_cast<const float2*>(bias + col);
            float2 o0, o1;
            o0.x = acc[mt][nt][0] + bb.x;
            o0.y = acc[mt][nt][1] + bb.y;
            o1.x = acc[mt][nt][2] + bb.x;
            o1.y = acc[mt][nt][3] + bb.y;
            *reinterpret_cast<float2*>(out + (size_t)row * KDIM + col) = o0;
            *reinterpret_cast<float2*>(out + (size_t)(row + 8) * KDIM + col) = o1;
        }
    }
}

extern "C" void kernel_launch(void* const* d_in, const int* in_sizes, int n_in,
                              void* d_out, int out_size)
{
    const float* x    = (const float*)d_in[0];   // [512, 4096]
    const float* w    = (const float*)d_in[1];   // [512, 512, 8, 8]
    const float* bias = (const float*)d_in[2];   // [512, 8] -> flat [4096]
    float* out = (float*)d_out;                  // [512, 4096]

    cvt_kernel<<<2560, 256>>>(x, w);

    cudaFuncSetAttribute(octonion_gemm_f16,
                         cudaFuncAttributeMaxDynamicSharedMemorySize, SMEM_BYTES);
    dim3 grid(KDIM / 128, 512 / 64);             // (32, 8) = 256 CTAs
    octonion_gemm_f16<<<grid, 128, SMEM_BYTES>>>(bias, out);
}